// round 7
// baseline (speedup 1.0000x reference)
#include <cuda_runtime.h>
#include <cuda_bf16.h>

#define NN 8192
#define T  64
#define NT (NN / T)   // 128

// Deterministic partial row sums: g_part[k][i] = degree contribution to row i
// from tile-column k. Written exactly once per slot. 4 MB scratch.
__device__ float g_part[NT * NN];
__device__ float g_dis[NN];

// ---------------------------------------------------------------------------
// Pass 1 (degrees): tile pair (bi <= bj). Only B = adj[J,I] staged in smem;
// A = adj[I,J] read straight from global in compute layout. Each smem element
// read exactly once; m accumulated into BOTH row partials (shfl-reduce) and
// column partials (per-thread register, since each thread owns one column).
// Thread map: c = t & 63 (column), rg = t >> 6 (16-row group).
// ---------------------------------------------------------------------------
__global__ __launch_bounds__(256) void pass1_degrees(const float* __restrict__ adj) {
    const int bi = blockIdx.y, bj = blockIdx.x;
    if (bj < bi) return;

    __shared__ float Bs[T][T + 1];
    __shared__ float rpart[T][2];
    __shared__ float cpart[4][T];

    const int t    = threadIdx.x;
    const int c    = t & 63;
    const int rg   = t >> 6;
    const int half = (t >> 5) & 1;        // which 32-column half this warp covers
    const size_t I0 = (size_t)bi * T, J0 = (size_t)bj * T;

    // Load B tile (coalesced; STS bank = (rr + c) % 32 via lane-c spread -> conflict-free)
    #pragma unroll
    for (int k = 0; k < 16; ++k) {
        int rr = rg * 16 + k;
        Bs[rr][c] = adj[(J0 + rr) * NN + I0 + c];
    }
    __syncthreads();

    const bool diag = (bi == bj);
    float colAcc = 0.0f;

    #pragma unroll
    for (int k = 0; k < 16; ++k) {
        int r = rg * 16 + k;
        float a = adj[(I0 + r) * NN + J0 + c];          // coalesced
        float m = fmaxf(a, Bs[c][r]);                    // bank (c+r)%32 -> conflict-free
        if (diag && r == c) m = 1.0f;
        colAcc += m;
        float s = m;                                     // row-sum reduce across the 32 lanes (c-half)
        s += __shfl_xor_sync(0xffffffffu, s, 1);
        s += __shfl_xor_sync(0xffffffffu, s, 2);
        s += __shfl_xor_sync(0xffffffffu, s, 4);
        s += __shfl_xor_sync(0xffffffffu, s, 8);
        s += __shfl_xor_sync(0xffffffffu, s, 16);
        if ((t & 31) == 0) rpart[r][half] = s;
    }
    cpart[rg][c] = colAcc;
    __syncthreads();

    if (t < T) {
        g_part[bj * NN + I0 + t] = rpart[t][0] + rpart[t][1];
        if (!diag)
            g_part[bi * NN + J0 + t] = cpart[0][t] + cpart[1][t] + cpart[2][t] + cpart[3][t];
    }
}

// ---------------------------------------------------------------------------
// Reduce the 128 partials per row, rsqrt. Coalesced.
// ---------------------------------------------------------------------------
__global__ __launch_bounds__(256) void reduce_rsqrt_kernel() {
    const int i = blockIdx.x * blockDim.x + threadIdx.x;
    if (i >= NN) return;
    float s = 0.0f;
    #pragma unroll 8
    for (int k = 0; k < NT; ++k)
        s += g_part[k * NN + i];
    g_dis[i] = rsqrtf(s);
}

// ---------------------------------------------------------------------------
// Pass 2 (write): out is SYMMETRIC, so the (J,I) block is the transpose of
// the (I,J) block. Compute scaled value s once, write out[I,J] coalesced,
// stage s in place over the Bs slot just read (bijective per-thread read ->
// no hazard), then one transposed conflict-free re-read writes out[J,I].
// Blocks walk tile pairs in REVERSE of pass1 order for L2 reuse.
// ---------------------------------------------------------------------------
__global__ __launch_bounds__(256) void pass2_write(const float* __restrict__ adj,
                                                   float* __restrict__ out) {
    const int bx = blockIdx.x, by = blockIdx.y;
    if (bx > by) return;                  // reversed triangle
    const int bi = NT - 1 - by, bj = NT - 1 - bx;   // bj >= bi

    __shared__ float Bs[T][T + 1];
    __shared__ float dI[T], dJ[T];

    const int t  = threadIdx.x;
    const int c  = t & 63;
    const int rg = t >> 6;
    const size_t I0 = (size_t)bi * T, J0 = (size_t)bj * T;

    #pragma unroll
    for (int k = 0; k < 16; ++k) {
        int rr = rg * 16 + k;
        Bs[rr][c] = adj[(J0 + rr) * NN + I0 + c];
    }
    if (t < T)          dI[t]     = g_dis[I0 + t];
    else if (t < 2 * T) dJ[t - T] = g_dis[J0 + (t - T)];
    __syncthreads();

    const bool diag = (bi == bj);
    const float djc = dJ[c];

    #pragma unroll
    for (int k = 0; k < 16; ++k) {
        int r = rg * 16 + k;
        float a = adj[(I0 + r) * NN + J0 + c];
        float m = fmaxf(a, Bs[c][r]);
        if (diag && r == c) m = 1.0f;
        float s = m * dI[r] * djc;
        out[(I0 + r) * NN + J0 + c] = s;  // coalesced
        Bs[c][r] = s;                     // stage transposed (same slot just read)
    }

    if (!diag) {
        __syncthreads();
        #pragma unroll
        for (int k = 0; k < 16; ++k) {
            int rr = rg * 16 + k;         // row within the (J,I) block
            out[(J0 + rr) * NN + I0 + c] = Bs[rr][c];   // conflict-free, coalesced
        }
    }
}

extern "C" void kernel_launch(void* const* d_in, const int* in_sizes, int n_in,
                              void* d_out, int out_size) {
    const float* adj = (const float*)d_in[0];
    float*       out = (float*)d_out;

    dim3 grid(NT, NT);
    pass1_degrees<<<grid, 256>>>(adj);
    reduce_rsqrt_kernel<<<NN / 256, 256>>>();
    pass2_write<<<grid, 256>>>(adj, out);
}

// round 8
// speedup vs baseline: 1.0482x; 1.0482x over previous
#include <cuda_runtime.h>
#include <cuda_bf16.h>

#define NN 8192
#define T  64
#define NT (NN / T)            // 128
#define NPAIR (NT * (NT + 1) / 2)   // 8256 tile pairs

// Deterministic partial row sums: g_part[k][i] = degree contribution to row i
// from tile-column k. Written exactly once per slot. 4 MB scratch.
__device__ float g_part[NT * NN];
__device__ float g_dis[NN];

// Decode linear pair index -> (bi, bj), bi <= bj, row-major over the upper triangle.
__device__ __forceinline__ void pair_decode(int idx, int& bi, int& bj) {
    const int M2 = 2 * NT + 1;
    int i = (int)(((float)M2 - sqrtf((float)M2 * (float)M2 - 8.0f * (float)idx)) * 0.5f);
    // integer fix-up (float sqrt can be off by one)
    while ((i * (2 * NT - i + 1)) / 2 > idx) --i;
    while (((i + 1) * (2 * NT - i)) / 2 <= idx) ++i;
    bi = i;
    bj = idx - (i * (2 * NT - i + 1)) / 2 + i;
}

// ---------------------------------------------------------------------------
// Pass 1 (degrees): tile pair (bi <= bj). B = adj[J,I] staged in smem (conflict
// free); A = adj[I,J] streamed from global in compute layout. The compute loop
// writes m back in place over the Bs slot it just read, so after one sync the
// row sums of M are conflict-free smem reads — no shfl reduction at all.
// ---------------------------------------------------------------------------
__global__ __launch_bounds__(256) void pass1_degrees(const float* __restrict__ adj) {
    int bi, bj;
    pair_decode(blockIdx.x, bi, bj);

    __shared__ float Bs[T][T + 1];
    __shared__ float rpartS[4][T];
    __shared__ float cpartS[4][T];

    const int t  = threadIdx.x;
    const int c  = t & 63;
    const int rg = t >> 6;
    const size_t I0 = (size_t)bi * T, J0 = (size_t)bj * T;

    // Stage B (coalesced LDG; STS bank = (rr + c)%32 across lanes -> conflict-free)
    #pragma unroll
    for (int k = 0; k < 16; ++k) {
        int rr = rg * 16 + k;
        Bs[rr][c] = adj[(J0 + rr) * NN + I0 + c];
    }
    __syncthreads();

    const bool diag = (bi == bj);
    float colAcc = 0.0f;

    // m = max(A, B^T); accumulate column sums in registers; store m in place.
    #pragma unroll
    for (int k = 0; k < 16; ++k) {
        int r = rg * 16 + k;
        float a = adj[(I0 + r) * NN + J0 + c];   // coalesced
        float m = fmaxf(a, Bs[c][r]);            // bank (c+r)%32 -> conflict-free
        if (diag && r == c) m = 1.0f;
        colAcc += m;
        Bs[c][r] = m;                            // same slot just read -> no hazard
    }
    cpartS[rg][c] = colAcc;
    __syncthreads();

    // Bs[c][r] now holds m(r,c): row sum of M over c = smem column read.
    float rowAcc = 0.0f;
    #pragma unroll
    for (int k = 0; k < 16; ++k)
        rowAcc += Bs[rg * 16 + k][c];            // lanes vary c -> conflict-free
    rpartS[rg][c] = rowAcc;
    __syncthreads();

    if (t < T) {
        g_part[bj * NN + I0 + t] =
            (rpartS[0][t] + rpartS[1][t]) + (rpartS[2][t] + rpartS[3][t]);
        if (!diag)
            g_part[bi * NN + J0 + t] =
                (cpartS[0][t] + cpartS[1][t]) + (cpartS[2][t] + cpartS[3][t]);
    }
}

// ---------------------------------------------------------------------------
// Reduce the 128 partials per row, rsqrt. Coalesced.
// ---------------------------------------------------------------------------
__global__ __launch_bounds__(256) void reduce_rsqrt_kernel() {
    const int i = blockIdx.x * blockDim.x + threadIdx.x;
    if (i >= NN) return;
    float s = 0.0f;
    #pragma unroll 8
    for (int k = 0; k < NT; ++k)
        s += g_part[k * NN + i];
    g_dis[i] = rsqrtf(s);
}

// ---------------------------------------------------------------------------
// Pass 2 (write): out is symmetric. Compute scaled value s once, write
// out[I,J] coalesced, stage s in place over the Bs slot just read, then one
// conflict-free transposed re-read writes out[J,I]. Walks the triangle in
// REVERSE of pass1 order so pass1's tail tiles are still L2-resident.
// ---------------------------------------------------------------------------
__global__ __launch_bounds__(256) void pass2_write(const float* __restrict__ adj,
                                                   float* __restrict__ out) {
    int bi, bj;
    pair_decode(NPAIR - 1 - (int)blockIdx.x, bi, bj);

    __shared__ float Bs[T][T + 1];
    __shared__ float dI[T], dJ[T];

    const int t  = threadIdx.x;
    const int c  = t & 63;
    const int rg = t >> 6;
    const size_t I0 = (size_t)bi * T, J0 = (size_t)bj * T;

    #pragma unroll
    for (int k = 0; k < 16; ++k) {
        int rr = rg * 16 + k;
        Bs[rr][c] = adj[(J0 + rr) * NN + I0 + c];
    }
    if (t < T)          dI[t]     = g_dis[I0 + t];
    else if (t < 2 * T) dJ[t - T] = g_dis[J0 + (t - T)];
    __syncthreads();

    const bool diag = (bi == bj);
    const float djc = dJ[c];

    #pragma unroll
    for (int k = 0; k < 16; ++k) {
        int r = rg * 16 + k;
        float a = adj[(I0 + r) * NN + J0 + c];
        float m = fmaxf(a, Bs[c][r]);
        if (diag && r == c) m = 1.0f;
        float s = m * dI[r] * djc;
        out[(I0 + r) * NN + J0 + c] = s;   // coalesced
        Bs[c][r] = s;                      // stage transposed (same slot just read)
    }

    if (!diag) {
        __syncthreads();
        #pragma unroll
        for (int k = 0; k < 16; ++k) {
            int rr = rg * 16 + k;          // row within the (J,I) block
            out[(J0 + rr) * NN + I0 + c] = Bs[rr][c];   // conflict-free, coalesced
        }
    }
}

extern "C" void kernel_launch(void* const* d_in, const int* in_sizes, int n_in,
                              void* d_out, int out_size) {
    const float* adj = (const float*)d_in[0];
    float*       out = (float*)d_out;

    pass1_degrees<<<NPAIR, 256>>>(adj);
    reduce_rsqrt_kernel<<<NN / 256, 256>>>();
    pass2_write<<<NPAIR, 256>>>(adj, out);
}

// round 9
// speedup vs baseline: 1.0503x; 1.0020x over previous
#include <cuda_runtime.h>
#include <cuda_bf16.h>

#define NN 8192
#define T  64
#define NT (NN / T)            // 128
#define NPAIR (NT * (NT + 1) / 2)   // 8256 tile pairs

// Deterministic partial row sums: g_part[k][i] = degree contribution to row i
// from tile-column k. Written exactly once per slot. 4 MB scratch.
__device__ float g_part[NT * NN];
__device__ float g_dis[NN];

// Decode linear pair index -> (bi, bj), bi <= bj, row-major over the upper triangle.
__device__ __forceinline__ void pair_decode(int idx, int& bi, int& bj) {
    const int M2 = 2 * NT + 1;
    int i = (int)(((float)M2 - sqrtf((float)M2 * (float)M2 - 8.0f * (float)idx)) * 0.5f);
    // integer fix-up (float sqrt can be off by one)
    while ((i * (2 * NT - i + 1)) / 2 > idx) --i;
    while (((i + 1) * (2 * NT - i)) / 2 <= idx) ++i;
    bi = i;
    bj = idx - (i * (2 * NT - i + 1)) / 2 + i;
}

// ---------------------------------------------------------------------------
// Pass 1 (degrees): tile pair (bi <= bj). B = adj[J,I] staged in smem (conflict
// free); A = adj[I,J] streamed from global in compute layout. The compute loop
// writes m back in place over the Bs slot it just read, so after one sync the
// row sums of M are conflict-free smem reads — no shfl reduction at all.
// ---------------------------------------------------------------------------
__global__ __launch_bounds__(256) void pass1_degrees(const float* __restrict__ adj) {
    int bi, bj;
    pair_decode(blockIdx.x, bi, bj);

    __shared__ float Bs[T][T + 1];
    __shared__ float rpartS[4][T];
    __shared__ float cpartS[4][T];

    const int t  = threadIdx.x;
    const int c  = t & 63;
    const int rg = t >> 6;
    const size_t I0 = (size_t)bi * T, J0 = (size_t)bj * T;

    // Stage B (coalesced LDG; STS bank = (rr + c)%32 across lanes -> conflict-free)
    #pragma unroll
    for (int k = 0; k < 16; ++k) {
        int rr = rg * 16 + k;
        Bs[rr][c] = adj[(J0 + rr) * NN + I0 + c];
    }
    __syncthreads();

    const bool diag = (bi == bj);
    float colAcc = 0.0f;

    // m = max(A, B^T); accumulate column sums in registers; store m in place.
    #pragma unroll
    for (int k = 0; k < 16; ++k) {
        int r = rg * 16 + k;
        float a = adj[(I0 + r) * NN + J0 + c];   // coalesced
        float m = fmaxf(a, Bs[c][r]);            // bank (c+r)%32 -> conflict-free
        if (diag && r == c) m = 1.0f;
        colAcc += m;
        Bs[c][r] = m;                            // same slot just read -> no hazard
    }
    cpartS[rg][c] = colAcc;
    __syncthreads();

    // Bs[c][r] now holds m(r,c): row sum of M over c = smem column read.
    float rowAcc = 0.0f;
    #pragma unroll
    for (int k = 0; k < 16; ++k)
        rowAcc += Bs[rg * 16 + k][c];            // lanes vary c -> conflict-free
    rpartS[rg][c] = rowAcc;
    __syncthreads();

    if (t < T) {
        g_part[bj * NN + I0 + t] =
            (rpartS[0][t] + rpartS[1][t]) + (rpartS[2][t] + rpartS[3][t]);
        if (!diag)
            g_part[bi * NN + J0 + t] =
                (cpartS[0][t] + cpartS[1][t]) + (cpartS[2][t] + cpartS[3][t]);
    }
}

// ---------------------------------------------------------------------------
// Reduce the 128 partials per row, rsqrt. Coalesced.
// ---------------------------------------------------------------------------
__global__ __launch_bounds__(256) void reduce_rsqrt_kernel() {
    const int i = blockIdx.x * blockDim.x + threadIdx.x;
    if (i >= NN) return;
    float s = 0.0f;
    #pragma unroll 8
    for (int k = 0; k < NT; ++k)
        s += g_part[k * NN + i];
    g_dis[i] = rsqrtf(s);
}

// ---------------------------------------------------------------------------
// Pass 2 (write): out is symmetric. Compute scaled value s once, write
// out[I,J] coalesced, stage s in place over the Bs slot just read, then one
// conflict-free transposed re-read writes out[J,I]. Walks the triangle in
// REVERSE of pass1 order so pass1's tail tiles are still L2-resident.
// ---------------------------------------------------------------------------
__global__ __launch_bounds__(256) void pass2_write(const float* __restrict__ adj,
                                                   float* __restrict__ out) {
    int bi, bj;
    pair_decode(NPAIR - 1 - (int)blockIdx.x, bi, bj);

    __shared__ float Bs[T][T + 1];
    __shared__ float dI[T], dJ[T];

    const int t  = threadIdx.x;
    const int c  = t & 63;
    const int rg = t >> 6;
    const size_t I0 = (size_t)bi * T, J0 = (size_t)bj * T;

    #pragma unroll
    for (int k = 0; k < 16; ++k) {
        int rr = rg * 16 + k;
        Bs[rr][c] = adj[(J0 + rr) * NN + I0 + c];
    }
    if (t < T)          dI[t]     = g_dis[I0 + t];
    else if (t < 2 * T) dJ[t - T] = g_dis[J0 + (t - T)];
    __syncthreads();

    const bool diag = (bi == bj);
    const float djc = dJ[c];

    #pragma unroll
    for (int k = 0; k < 16; ++k) {
        int r = rg * 16 + k;
        float a = adj[(I0 + r) * NN + J0 + c];
        float m = fmaxf(a, Bs[c][r]);
        if (diag && r == c) m = 1.0f;
        float s = m * dI[r] * djc;
        out[(I0 + r) * NN + J0 + c] = s;   // coalesced
        Bs[c][r] = s;                      // stage transposed (same slot just read)
    }

    if (!diag) {
        __syncthreads();
        #pragma unroll
        for (int k = 0; k < 16; ++k) {
            int rr = rg * 16 + k;          // row within the (J,I) block
            out[(J0 + rr) * NN + I0 + c] = Bs[rr][c];   // conflict-free, coalesced
        }
    }
}

extern "C" void kernel_launch(void* const* d_in, const int* in_sizes, int n_in,
                              void* d_out, int out_size) {
    const float* adj = (const float*)d_in[0];
    float*       out = (float*)d_out;

    pass1_degrees<<<NPAIR, 256>>>(adj);
    reduce_rsqrt_kernel<<<NN / 256, 256>>>();
    pass2_write<<<NPAIR, 256>>>(adj, out);
}

// round 10
// speedup vs baseline: 1.0992x; 1.0466x over previous
#include <cuda_runtime.h>
#include <cuda_bf16.h>

#define NN 8192
#define T  64
#define NT (NN / T)                 // 128
#define NPAIR (NT * (NT + 1) / 2)   // 8256 tile pairs

// Deterministic partial row sums: g_part[k][i] = degree contribution to row i
// from tile-column k. Written exactly once per slot. 4 MB scratch.
__device__ float g_part[NT * NN];
__device__ float g_dis[NN];

// Decode linear pair index -> (bi, bj), bi <= bj, row-major over upper triangle.
__device__ __forceinline__ void pair_decode(int idx, int& bi, int& bj) {
    const int M2 = 2 * NT + 1;
    int i = (int)(((float)M2 - sqrtf((float)M2 * (float)M2 - 8.0f * (float)idx)) * 0.5f);
    while ((i * (2 * NT - i + 1)) / 2 > idx) --i;
    while (((i + 1) * (2 * NT - i)) / 2 <= idx) ++i;
    bi = i;
    bj = idx - (i * (2 * NT - i + 1)) / 2 + i;
}

// ---------------------------------------------------------------------------
// Pass 1 (degrees), fully float4 on the global side.
// Thread map: c4 = 4*(t&15) (4-col group), rg = t>>4; rows r = rg + 16k.
// B = adj[J,I] staged in smem (pad 65: transpose reads are 2-way max);
// A = adj[I,J] streamed LDG.128. Row partials -> rpart[64][17] (17 coprime 32
// => conflict-free final read); col partials -> cpart[16][64].
// ---------------------------------------------------------------------------
__global__ __launch_bounds__(256) void pass1_degrees(const float* __restrict__ adj) {
    int bi, bj;
    pair_decode(blockIdx.x, bi, bj);

    __shared__ float Bs[T][T + 1];
    __shared__ float rpart[T][17];
    __shared__ float cpart[16][T];

    const int t  = threadIdx.x;
    const int c4 = (t & 15) * 4;
    const int rg = t >> 4;
    const size_t I0 = (size_t)bi * T, J0 = (size_t)bj * T;

    #pragma unroll
    for (int k = 0; k < 4; ++k) {
        int rr = rg + 16 * k;
        float4 b = *reinterpret_cast<const float4*>(&adj[(J0 + rr) * NN + I0 + c4]);
        Bs[rr][c4 + 0] = b.x; Bs[rr][c4 + 1] = b.y;
        Bs[rr][c4 + 2] = b.z; Bs[rr][c4 + 3] = b.w;
    }
    __syncthreads();

    const bool diag = (bi == bj);
    float ca0 = 0.f, ca1 = 0.f, ca2 = 0.f, ca3 = 0.f;

    #pragma unroll
    for (int k = 0; k < 4; ++k) {
        int r = rg + 16 * k;
        float4 a = *reinterpret_cast<const float4*>(&adj[(I0 + r) * NN + J0 + c4]);
        float m0 = fmaxf(a.x, Bs[c4 + 0][r]);
        float m1 = fmaxf(a.y, Bs[c4 + 1][r]);
        float m2 = fmaxf(a.z, Bs[c4 + 2][r]);
        float m3 = fmaxf(a.w, Bs[c4 + 3][r]);
        if (diag) {
            if (r == c4 + 0) m0 = 1.0f;
            if (r == c4 + 1) m1 = 1.0f;
            if (r == c4 + 2) m2 = 1.0f;
            if (r == c4 + 3) m3 = 1.0f;
        }
        ca0 += m0; ca1 += m1; ca2 += m2; ca3 += m3;
        rpart[r][t & 15] = (m0 + m1) + (m2 + m3);
    }
    cpart[rg][c4 + 0] = ca0; cpart[rg][c4 + 1] = ca1;
    cpart[rg][c4 + 2] = ca2; cpart[rg][c4 + 3] = ca3;
    __syncthreads();

    if (t < T) {
        float s = 0.f;
        #pragma unroll
        for (int j = 0; j < 16; ++j) s += rpart[t][j];
        g_part[bj * NN + I0 + t] = s;
    } else if (t < 2 * T && !diag) {
        int cc = t - T;
        float s = 0.f;
        #pragma unroll
        for (int j = 0; j < 16; ++j) s += cpart[j][cc];
        g_part[bi * NN + J0 + cc] = s;
    }
}

// ---------------------------------------------------------------------------
// Degree reduce + rsqrt: 128 blocks; 4 threads per row (k-slices), combined
// through smem. Fully coalesced, deterministic fixed-order sums.
// ---------------------------------------------------------------------------
__global__ __launch_bounds__(256) void reduce_rsqrt_kernel() {
    __shared__ float part[4][T];
    const int t = threadIdx.x;
    const int i = blockIdx.x * T + (t & 63);
    const int q = t >> 6;

    float s = 0.f;
    #pragma unroll
    for (int kk = 0; kk < NT / 4; ++kk)
        s += g_part[(q + 4 * kk) * NN + i];
    part[q][t & 63] = s;
    __syncthreads();

    if (t < T) {
        float tot = (part[0][t] + part[1][t]) + (part[2][t] + part[3][t]);
        g_dis[blockIdx.x * T + t] = rsqrtf(tot);
    }
}

// ---------------------------------------------------------------------------
// Pass 2 (write), float4 throughout. out is symmetric: compute scaled s once,
// STG.128 to out[I,J], stage s in place over the Bs slot just read (bijective
// per-thread -> no hazard), then LDS + STG.128 for out[J,I]. Reverse triangle
// order so pass1's tail tiles are still L2-resident.
// ---------------------------------------------------------------------------
__global__ __launch_bounds__(256) void pass2_write(const float* __restrict__ adj,
                                                   float* __restrict__ out) {
    int bi, bj;
    pair_decode(NPAIR - 1 - (int)blockIdx.x, bi, bj);

    __shared__ float Bs[T][T + 1];
    __shared__ float dI[T], dJ[T];

    const int t  = threadIdx.x;
    const int c4 = (t & 15) * 4;
    const int rg = t >> 4;
    const size_t I0 = (size_t)bi * T, J0 = (size_t)bj * T;

    #pragma unroll
    for (int k = 0; k < 4; ++k) {
        int rr = rg + 16 * k;
        float4 b = *reinterpret_cast<const float4*>(&adj[(J0 + rr) * NN + I0 + c4]);
        Bs[rr][c4 + 0] = b.x; Bs[rr][c4 + 1] = b.y;
        Bs[rr][c4 + 2] = b.z; Bs[rr][c4 + 3] = b.w;
    }
    if (t < T)          dI[t]     = g_dis[I0 + t];
    else if (t < 2 * T) dJ[t - T] = g_dis[J0 + (t - T)];
    __syncthreads();

    const bool diag = (bi == bj);
    const float dj0 = dJ[c4 + 0], dj1 = dJ[c4 + 1];
    const float dj2 = dJ[c4 + 2], dj3 = dJ[c4 + 3];

    #pragma unroll
    for (int k = 0; k < 4; ++k) {
        int r = rg + 16 * k;
        float4 a = *reinterpret_cast<const float4*>(&adj[(I0 + r) * NN + J0 + c4]);
        const float dir = dI[r];
        float m0 = fmaxf(a.x, Bs[c4 + 0][r]);
        float m1 = fmaxf(a.y, Bs[c4 + 1][r]);
        float m2 = fmaxf(a.z, Bs[c4 + 2][r]);
        float m3 = fmaxf(a.w, Bs[c4 + 3][r]);
        if (diag) {
            if (r == c4 + 0) m0 = 1.0f;
            if (r == c4 + 1) m1 = 1.0f;
            if (r == c4 + 2) m2 = 1.0f;
            if (r == c4 + 3) m3 = 1.0f;
        }
        float4 o;
        o.x = m0 * dir * dj0; o.y = m1 * dir * dj1;
        o.z = m2 * dir * dj2; o.w = m3 * dir * dj3;
        *reinterpret_cast<float4*>(&out[(I0 + r) * NN + J0 + c4]) = o;
        // Stage transposed for the mirror block (same slots just read)
        Bs[c4 + 0][r] = o.x; Bs[c4 + 1][r] = o.y;
        Bs[c4 + 2][r] = o.z; Bs[c4 + 3][r] = o.w;
    }

    if (!diag) {
        __syncthreads();
        #pragma unroll
        for (int k = 0; k < 4; ++k) {
            int rr = rg + 16 * k;         // row within the (J,I) block
            float4 o;
            o.x = Bs[rr][c4 + 0]; o.y = Bs[rr][c4 + 1];
            o.z = Bs[rr][c4 + 2]; o.w = Bs[rr][c4 + 3];
            *reinterpret_cast<float4*>(&out[(J0 + rr) * NN + I0 + c4]) = o;
        }
    }
}

extern "C" void kernel_launch(void* const* d_in, const int* in_sizes, int n_in,
                              void* d_out, int out_size) {
    const float* adj = (const float*)d_in[0];
    float*       out = (float*)d_out;

    pass1_degrees<<<NPAIR, 256>>>(adj);
    reduce_rsqrt_kernel<<<NN / T, 256>>>();
    pass2_write<<<NPAIR, 256>>>(adj, out);
}

// round 11
// speedup vs baseline: 1.1305x; 1.0285x over previous
#include <cuda_runtime.h>
#include <cuda_bf16.h>

#define NN 8192
#define T  64
#define NT (NN / T)                 // 128
#define NPAIR (NT * (NT + 1) / 2)   // 8256 tile pairs

// Deterministic partial row sums: g_part[k][i] = degree contribution to row i
// from tile-column k. Written exactly once per slot. 4 MB scratch.
__device__ float g_part[NT * NN];
__device__ float g_dis[NN];

// Decode linear pair index -> (bi, bj), bi <= bj, row-major over upper triangle.
__device__ __forceinline__ void pair_decode(int idx, int& bi, int& bj) {
    const int M2 = 2 * NT + 1;
    int i = (int)(((float)M2 - sqrtf((float)M2 * (float)M2 - 8.0f * (float)idx)) * 0.5f);
    while ((i * (2 * NT - i + 1)) / 2 > idx) --i;
    while (((i + 1) * (2 * NT - i)) / 2 <= idx) ++i;
    bi = i;
    bj = idx - (i * (2 * NT - i + 1)) / 2 + i;
}

// ---------------------------------------------------------------------------
// Pass 1 (degrees): scalar conflict-free thread map (c = t&63, rows rg*16+k).
// MLP fix: B-stage LDG->STS AND a 16-deep A prefetch into registers are ALL
// issued before the single barrier, so 32 independent LDGs per thread are in
// flight while the barrier drains. Compute loop touches only registers and
// conflict-free smem (pad 65). In-place transpose store makes row sums plain
// smem column reads; no shfl anywhere.
// ---------------------------------------------------------------------------
__global__ __launch_bounds__(256) void pass1_degrees(const float* __restrict__ adj) {
    int bi, bj;
    pair_decode(blockIdx.x, bi, bj);

    __shared__ float Bs[T][T + 1];
    __shared__ float rpartS[4][T];
    __shared__ float cpartS[4][T];

    const int t  = threadIdx.x;
    const int c  = t & 63;
    const int rg = t >> 6;
    const size_t I0 = (size_t)bi * T, J0 = (size_t)bj * T;

    // Prefetch the 16 A values this thread will consume (coalesced LDG.32).
    float a[16];
    #pragma unroll
    for (int k = 0; k < 16; ++k)
        a[k] = adj[(I0 + rg * 16 + k) * NN + J0 + c];

    // Stage B (coalesced LDG; STS bank (rr + c)%32 -> conflict-free).
    #pragma unroll
    for (int k = 0; k < 16; ++k) {
        int rr = rg * 16 + k;
        Bs[rr][c] = adj[(J0 + rr) * NN + I0 + c];
    }
    __syncthreads();

    const bool diag = (bi == bj);
    float colAcc = 0.0f;

    // m = max(A, B^T); column sums in a register; store m back in place.
    #pragma unroll
    for (int k = 0; k < 16; ++k) {
        int r = rg * 16 + k;
        float m = fmaxf(a[k], Bs[c][r]);         // bank (c+r)%32 -> conflict-free
        if (diag && r == c) m = 1.0f;
        colAcc += m;
        Bs[c][r] = m;                            // same slot just read -> no hazard
    }
    cpartS[rg][c] = colAcc;
    __syncthreads();

    // Bs[c][r] holds m(r,c): row sums of M are conflict-free smem reads.
    float rowAcc = 0.0f;
    #pragma unroll
    for (int k = 0; k < 16; ++k)
        rowAcc += Bs[rg * 16 + k][c];
    rpartS[rg][c] = rowAcc;
    __syncthreads();

    if (t < T) {
        g_part[bj * NN + I0 + t] =
            (rpartS[0][t] + rpartS[1][t]) + (rpartS[2][t] + rpartS[3][t]);
        if (!diag)
            g_part[bi * NN + J0 + t] =
                (cpartS[0][t] + cpartS[1][t]) + (cpartS[2][t] + cpartS[3][t]);
    }
}

// ---------------------------------------------------------------------------
// Degree reduce + rsqrt: 128 blocks; 4 k-slices per row combined via smem.
// Fully coalesced, deterministic fixed-order sums.
// ---------------------------------------------------------------------------
__global__ __launch_bounds__(256) void reduce_rsqrt_kernel() {
    __shared__ float part[4][T];
    const int t = threadIdx.x;
    const int i = blockIdx.x * T + (t & 63);
    const int q = t >> 6;

    float s = 0.f;
    #pragma unroll
    for (int kk = 0; kk < NT / 4; ++kk)
        s += g_part[(q + 4 * kk) * NN + i];
    part[q][t & 63] = s;
    __syncthreads();

    if (t < T) {
        float tot = (part[0][t] + part[1][t]) + (part[2][t] + part[3][t]);
        g_dis[blockIdx.x * T + t] = rsqrtf(tot);
    }
}

// ---------------------------------------------------------------------------
// Pass 2 (write), float4 throughout (measured at the LTS cap). out is
// symmetric: compute scaled s once, STG.128 to out[I,J], stage s transposed
// in place, then STG.128 the mirror block. Reverse triangle order for L2
// reuse of pass1's tail tiles.
// ---------------------------------------------------------------------------
__global__ __launch_bounds__(256) void pass2_write(const float* __restrict__ adj,
                                                   float* __restrict__ out) {
    int bi, bj;
    pair_decode(NPAIR - 1 - (int)blockIdx.x, bi, bj);

    __shared__ float Bs[T][T + 1];
    __shared__ float dI[T], dJ[T];

    const int t  = threadIdx.x;
    const int c4 = (t & 15) * 4;
    const int rg = t >> 4;
    const size_t I0 = (size_t)bi * T, J0 = (size_t)bj * T;

    #pragma unroll
    for (int k = 0; k < 4; ++k) {
        int rr = rg + 16 * k;
        float4 b = *reinterpret_cast<const float4*>(&adj[(J0 + rr) * NN + I0 + c4]);
        Bs[rr][c4 + 0] = b.x; Bs[rr][c4 + 1] = b.y;
        Bs[rr][c4 + 2] = b.z; Bs[rr][c4 + 3] = b.w;
    }
    if (t < T)          dI[t]     = g_dis[I0 + t];
    else if (t < 2 * T) dJ[t - T] = g_dis[J0 + (t - T)];
    __syncthreads();

    const bool diag = (bi == bj);
    const float dj0 = dJ[c4 + 0], dj1 = dJ[c4 + 1];
    const float dj2 = dJ[c4 + 2], dj3 = dJ[c4 + 3];

    #pragma unroll
    for (int k = 0; k < 4; ++k) {
        int r = rg + 16 * k;
        float4 a = *reinterpret_cast<const float4*>(&adj[(I0 + r) * NN + J0 + c4]);
        const float dir = dI[r];
        float m0 = fmaxf(a.x, Bs[c4 + 0][r]);
        float m1 = fmaxf(a.y, Bs[c4 + 1][r]);
        float m2 = fmaxf(a.z, Bs[c4 + 2][r]);
        float m3 = fmaxf(a.w, Bs[c4 + 3][r]);
        if (diag) {
            if (r == c4 + 0) m0 = 1.0f;
            if (r == c4 + 1) m1 = 1.0f;
            if (r == c4 + 2) m2 = 1.0f;
            if (r == c4 + 3) m3 = 1.0f;
        }
        float4 o;
        o.x = m0 * dir * dj0; o.y = m1 * dir * dj1;
        o.z = m2 * dir * dj2; o.w = m3 * dir * dj3;
        *reinterpret_cast<float4*>(&out[(I0 + r) * NN + J0 + c4]) = o;
        Bs[c4 + 0][r] = o.x; Bs[c4 + 1][r] = o.y;
        Bs[c4 + 2][r] = o.z; Bs[c4 + 3][r] = o.w;
    }

    if (!diag) {
        __syncthreads();
        #pragma unroll
        for (int k = 0; k < 4; ++k) {
            int rr = rg + 16 * k;
            float4 o;
            o.x = Bs[rr][c4 + 0]; o.y = Bs[rr][c4 + 1];
            o.z = Bs[rr][c4 + 2]; o.w = Bs[rr][c4 + 3];
            *reinterpret_cast<float4*>(&out[(J0 + rr) * NN + I0 + c4]) = o;
        }
    }
}

extern "C" void kernel_launch(void* const* d_in, const int* in_sizes, int n_in,
                              void* d_out, int out_size) {
    const float* adj = (const float*)d_in[0];
    float*       out = (float*)d_out;

    pass1_degrees<<<NPAIR, 256>>>(adj);
    reduce_rsqrt_kernel<<<NN / T, 256>>>();
    pass2_write<<<NPAIR, 256>>>(adj, out);
}